// round 14
// baseline (speedup 1.0000x reference)
#include <cuda_runtime.h>
#include <cuda_bf16.h>
#include <cstdint>

// Problem constants
#define S_LEN 2048
#define B_SZ  128
#define H_SZ  128
#define G_SZ  384   // 3*H
#define C_SZ  10
#define TCH_T 16    // timesteps per GEMM CTA

// Scratch: xp (input projections, reused by both layers) and y0 (layer-0 output seq)
__device__ float g_xp[(size_t)S_LEN * B_SZ * G_SZ];   // [(t*B + b)*3H + g]
__device__ float g_y0[(size_t)S_LEN * B_SZ * H_SZ];   // [(t*B + b)*H + j]

// ---- packed dual-fp32 helpers -------------------------------------------
__device__ __forceinline__ unsigned long long fma2(unsigned long long a,
                                                   unsigned long long b,
                                                   unsigned long long c) {
    unsigned long long d;
    asm("fma.rn.f32x2 %0, %1, %2, %3;" : "=l"(d) : "l"(a), "l"(b), "l"(c));
    return d;
}
__device__ __forceinline__ float lo32(unsigned long long v) {
    return __uint_as_float((unsigned)(v & 0xffffffffull));
}
__device__ __forceinline__ float hi32(unsigned long long v) {
    return __uint_as_float((unsigned)(v >> 32));
}

// ---- mma.sync / ldmatrix helpers (plain sm_80+ features, no 'a'-gating) ---
__device__ __forceinline__ uint32_t smem_u32(const void* p) {
    uint32_t a;
    asm("{ .reg .u64 t; cvta.to.shared.u64 t, %1; cvt.u32.u64 %0, t; }"
        : "=r"(a) : "l"(p));
    return a;
}
__device__ __forceinline__ void ldmx4(uint32_t* r, uint32_t addr) {
    asm volatile("ldmatrix.sync.aligned.m8n8.x4.shared.b16 {%0,%1,%2,%3}, [%4];"
                 : "=r"(r[0]), "=r"(r[1]), "=r"(r[2]), "=r"(r[3]) : "r"(addr));
}
__device__ __forceinline__ void mma_bf16(float* c, const uint32_t* a,
                                         uint32_t b0, uint32_t b1) {
    asm volatile(
        "mma.sync.aligned.m16n8k16.row.col.f32.bf16.bf16.f32 "
        "{%0,%1,%2,%3}, {%4,%5,%6,%7}, {%8,%9}, {%0,%1,%2,%3};"
        : "+f"(c[0]), "+f"(c[1]), "+f"(c[2]), "+f"(c[3])
        : "r"(a[0]), "r"(a[1]), "r"(a[2]), "r"(a[3]), "r"(b0), "r"(b1));
}

// Split one float4 into bf16 hi + lo pairs (packed as uint2 = 4 bf16)
__device__ __forceinline__ void split4(float4 v, uint2& hi, uint2& lo) {
    __nv_bfloat162 h01 = __floats2bfloat162_rn(v.x, v.y);
    __nv_bfloat162 h23 = __floats2bfloat162_rn(v.z, v.w);
    const float r0 = v.x - __bfloat162float(h01.x);
    const float r1 = v.y - __bfloat162float(h01.y);
    const float r2 = v.z - __bfloat162float(h23.x);
    const float r3 = v.w - __bfloat162float(h23.y);
    __nv_bfloat162 l01 = __floats2bfloat162_rn(r0, r1);
    __nv_bfloat162 l23 = __floats2bfloat162_rn(r2, r3);
    hi = make_uint2(*reinterpret_cast<uint32_t*>(&h01), *reinterpret_cast<uint32_t*>(&h23));
    lo = make_uint2(*reinterpret_cast<uint32_t*>(&l01), *reinterpret_cast<uint32_t*>(&l23));
}

// SMEM layout (bytes): bias + 2x double-buffered X tiles + W tiles, pitch 272 B
#define PITCHB 272
#define TILEB  (128 * PITCHB)          // 34816
#define SM_BIAS 0
#define SM_XHI0 512
#define SM_XLO0 (SM_XHI0 + TILEB)
#define SM_XHI1 (SM_XLO0 + TILEB)
#define SM_XLO1 (SM_XHI1 + TILEB)
#define SM_WHI  (SM_XLO1 + TILEB)
#define SM_WLO  (SM_WHI + TILEB)
#define SM_TOT  (SM_WLO + TILEB)       // 209408

// ---------------------------------------------------------------------------
// Tensor-core input-projection GEMM — unchanged from R11 (proven ~420 us each).
// ---------------------------------------------------------------------------
__global__ __launch_bounds__(256, 1)
void gemm_mma_kernel(const float* __restrict__ in,
                     const float* __restrict__ W,
                     const float* __restrict__ bias,
                     float* __restrict__ out,
                     long strideB, long strideT)
{
    extern __shared__ __align__(16) char smem[];
    const uint32_t sb = smem_u32(smem);
    float* sbias = reinterpret_cast<float*>(smem + SM_BIAS);

    const int tid  = threadIdx.x;
    const int w    = tid >> 5;
    const int lane = tid & 31;
    const int tbase = blockIdx.x * TCH_T;
    const int g0    = blockIdx.y * 128;

    if (tid < 128) sbias[tid] = bias[g0 + tid];
    for (int i = tid; i < 128 * 32; i += 256) {
        const int row = i >> 5, c4 = i & 31;
        const float4 v = *reinterpret_cast<const float4*>(
            W + (size_t)(g0 + row) * H_SZ + c4 * 4);
        uint2 hi, lo;
        split4(v, hi, lo);
        const int off = row * PITCHB + c4 * 8;
        *reinterpret_cast<uint2*>(smem + SM_WHI + off) = hi;
        *reinterpret_cast<uint2*>(smem + SM_WLO + off) = lo;
    }

    {
        const int t0 = tbase;
#pragma unroll
        for (int k = 0; k < 16; k++) {
            const int i = tid + k * 256;
            const int row = i >> 5, c4 = i & 31;
            const float4 v = *reinterpret_cast<const float4*>(
                in + (size_t)row * strideB + (size_t)t0 * strideT + c4 * 4);
            uint2 hi, lo;
            split4(v, hi, lo);
            const int off = row * PITCHB + c4 * 8;
            *reinterpret_cast<uint2*>(smem + SM_XHI0 + off) = hi;
            *reinterpret_cast<uint2*>(smem + SM_XLO0 + off) = lo;
        }
    }
    __syncthreads();

    const int mBase = (w & 1) * 64;
    const int nBase = (w >> 1) * 32;

    uint32_t aoff[4];
#pragma unroll
    for (int mt = 0; mt < 4; mt++)
        aoff[mt] = (uint32_t)((mBase + mt * 16 + (lane & 15)) * PITCHB
                              + (lane >> 4) * 16);
    uint32_t boff[2];
#pragma unroll
    for (int nt2 = 0; nt2 < 2; nt2++) {
        const int rt = lane & 7, tl = lane >> 3;
        const int n = nBase + nt2 * 16 + ((tl >> 1) << 3) + rt;
        boff[nt2] = (uint32_t)(n * PITCHB + (tl & 1) * 16);
    }

    for (int tt = 0; tt < TCH_T; tt++) {
        const int t   = tbase + tt;
        const int cur = tt & 1;
        const uint32_t xhiC = cur ? SM_XHI1 : SM_XHI0;
        const uint32_t xloC = cur ? SM_XLO1 : SM_XLO0;
        const uint32_t xhiN = cur ? SM_XHI0 : SM_XHI1;
        const uint32_t xloN = cur ? SM_XLO0 : SM_XLO1;

        float4 v[16];
        const bool more = (tt + 1 < TCH_T);
        if (more) {
#pragma unroll
            for (int k = 0; k < 16; k++) {
                const int i = tid + k * 256;
                const int row = i >> 5, c4 = i & 31;
                v[k] = *reinterpret_cast<const float4*>(
                    in + (size_t)row * strideB + (size_t)(t + 1) * strideT + c4 * 4);
            }
        }

        float acc[4][4][4];
#pragma unroll
        for (int mt = 0; mt < 4; mt++)
#pragma unroll
            for (int nt = 0; nt < 4; nt++)
#pragma unroll
                for (int e = 0; e < 4; e++) acc[mt][nt][e] = 0.0f;

#pragma unroll
        for (int s = 0; s < 3; s++) {
            const uint32_t aS = sb + (s == 2 ? xloC : xhiC);
            const uint32_t bS = sb + (s == 1 ? SM_WLO : SM_WHI);

            uint32_t a[2][4][4], b[2][2][4];
#pragma unroll
            for (int mt = 0; mt < 4; mt++) ldmx4(a[0][mt], aS + aoff[mt]);
#pragma unroll
            for (int nt2 = 0; nt2 < 2; nt2++) ldmx4(b[0][nt2], bS + boff[nt2]);

#pragma unroll
            for (int k16 = 0; k16 < 8; k16++) {
                const int pc = k16 & 1;
                const int pn = pc ^ 1;
                if (k16 < 7) {
                    const uint32_t kb = (uint32_t)((k16 + 1) * 32);
#pragma unroll
                    for (int mt = 0; mt < 4; mt++) ldmx4(a[pn][mt], aS + aoff[mt] + kb);
#pragma unroll
                    for (int nt2 = 0; nt2 < 2; nt2++) ldmx4(b[pn][nt2], bS + boff[nt2] + kb);
                }
#pragma unroll
                for (int mt = 0; mt < 4; mt++)
#pragma unroll
                    for (int nt = 0; nt < 4; nt++)
                        mma_bf16(acc[mt][nt], a[pc][mt],
                                 b[pc][nt >> 1][(nt & 1) * 2],
                                 b[pc][nt >> 1][(nt & 1) * 2 + 1]);
            }
        }

        if (more) {
#pragma unroll
            for (int k = 0; k < 16; k++) {
                const int i = tid + k * 256;
                const int row = i >> 5, c4 = i & 31;
                uint2 hi, lo;
                split4(v[k], hi, lo);
                const int off = row * PITCHB + c4 * 8;
                *reinterpret_cast<uint2*>(smem + xhiN + off) = hi;
                *reinterpret_cast<uint2*>(smem + xloN + off) = lo;
            }
        }

        const int mrow = lane >> 2;
        const int ncol = (lane & 3) * 2;
#pragma unroll
        for (int mt = 0; mt < 4; mt++) {
#pragma unroll
            for (int nt = 0; nt < 4; nt++) {
                const int col = nBase + nt * 8 + ncol;
                const float bv0 = sbias[col], bv1 = sbias[col + 1];
                const int row0 = mBase + mt * 16 + mrow;
                float* p0 = out + ((size_t)t * B_SZ + row0) * G_SZ + g0 + col;
                float* p1 = p0 + (size_t)8 * G_SZ;
                *reinterpret_cast<float2*>(p0) =
                    make_float2(acc[mt][nt][0] + bv0, acc[mt][nt][1] + bv1);
                *reinterpret_cast<float2*>(p1) =
                    make_float2(acc[mt][nt][2] + bv0, acc[mt][nt][3] + bv1);
            }
        }
        __syncthreads();
    }
}

// ---------------------------------------------------------------------------
// Recurrent scan — R1 skeleton (proven best) with ONE change: gate threads
// keep their 3 x values in registers (prefetched a full step ahead), removing
// the xg_s staging array (STS x384/step) and one LDS from the serial gate
// chain. Dot loop and gate math otherwise byte-identical to R1.
// One CTA per batch element, 384 threads (one per gate output).
// ---------------------------------------------------------------------------
__global__ __launch_bounds__(384, 1)
void recur_kernel(const float* __restrict__ xp,
                  const float* __restrict__ W_hh,
                  const float* __restrict__ b_hh,
                  int write_y,
                  const float* __restrict__ W_out,
                  const float* __restrict__ b_out,
                  float* __restrict__ out)
{
    __shared__ __align__(16) float h_s[H_SZ];
    __shared__ float hp_s[G_SZ];

    const int b = blockIdx.x;
    const int g = threadIdx.x;

    unsigned long long w[64];
    const unsigned long long* wrow =
        reinterpret_cast<const unsigned long long*>(W_hh + (size_t)g * H_SZ);
#pragma unroll
    for (int i = 0; i < 64; i++) w[i] = wrow[i];
    const float bh = b_hh[g];

    const float* xb = xp + (size_t)b * G_SZ;
    // Gate threads hold their 3 x values in registers (t=0 prefetch here)
    float xr = 0.f, xz = 0.f, xn = 0.f;
    if (g < H_SZ) {
        xr = __ldg(xb + g);
        xz = __ldg(xb + H_SZ + g);
        xn = __ldg(xb + 2 * H_SZ + g);
        h_s[g] = 0.0f;
    }
    __syncthreads();

    for (int t = 0; t < S_LEN; t++) {
        // Prefetch next step's x (gate threads; consumed next iteration,
        // ~700 cyc later -> DRAM latency fully hidden under the dot+barriers)
        float nxr = 0.f, nxz = 0.f, nxn = 0.f;
        if (g < H_SZ && t + 1 < S_LEN) {
            const float* q = xb + (size_t)(t + 1) * B_SZ * G_SZ;
            nxr = __ldg(q + g);
            nxz = __ldg(q + H_SZ + g);
            nxn = __ldg(q + 2 * H_SZ + g);
        }

        // hp[g] = h . W_hh[g]  (R1 2-chain dot, unchanged)
        unsigned long long a0 = 0ull, a1 = 0ull;
        const ulonglong2* hq = reinterpret_cast<const ulonglong2*>(h_s);
#pragma unroll
        for (int i = 0; i < 32; i++) {
            const ulonglong2 q = hq[i];   // broadcast LDS.128
            a0 = fma2(q.x, w[2 * i + 0], a0);
            a1 = fma2(q.y, w[2 * i + 1], a1);
        }
        hp_s[g] = lo32(a0) + hi32(a0) + lo32(a1) + hi32(a1) + bh;
        __syncthreads();

        if (g < H_SZ) {
            const float pr = xr + hp_s[g];
            const float pz = xz + hp_s[H_SZ + g];
            const float hn = hp_s[2 * H_SZ + g];
            const float r = 1.0f / (1.0f + __expf(-pr));
            const float z = 1.0f / (1.0f + __expf(-pz));
            const float n = tanhf(fmaf(r, hn, xn));
            const float hold = h_s[g];
            const float hnew = (1.0f - z) * n + z * hold;
            h_s[g] = hnew;
            if (write_y)
                g_y0[((size_t)t * B_SZ + b) * H_SZ + g] = hnew;
        }
        __syncthreads();

        xr = nxr; xz = nxz; xn = nxn;
    }

    // Fused final linear layer (layer 1 only)
    if (!write_y && g < C_SZ) {
        float acc = b_out[g];
#pragma unroll 8
        for (int j = 0; j < H_SZ; j++)
            acc = fmaf(h_s[j], W_out[g * H_SZ + j], acc);
        out[b * C_SZ + g] = acc;
    }
}

// ---------------------------------------------------------------------------
extern "C" void kernel_launch(void* const* d_in, const int* in_sizes, int n_in,
                              void* d_out, int out_size)
{
    const float* x     = (const float*)d_in[0];
    const float* W_ih0 = (const float*)d_in[1];
    const float* W_hh0 = (const float*)d_in[2];
    const float* b_ih0 = (const float*)d_in[3];
    const float* b_hh0 = (const float*)d_in[4];
    const float* W_ih1 = (const float*)d_in[5];
    const float* W_hh1 = (const float*)d_in[6];
    const float* b_ih1 = (const float*)d_in[7];
    const float* b_hh1 = (const float*)d_in[8];
    const float* W_out = (const float*)d_in[9];
    const float* b_out = (const float*)d_in[10];
    float* out = (float*)d_out;

    void* xp_ptr = nullptr;
    void* y0_ptr = nullptr;
    cudaGetSymbolAddress(&xp_ptr, g_xp);
    cudaGetSymbolAddress(&y0_ptr, g_y0);
    float* xp = (float*)xp_ptr;
    float* y0 = (float*)y0_ptr;

    cudaFuncSetAttribute(gemm_mma_kernel,
                         cudaFuncAttributeMaxDynamicSharedMemorySize, SM_TOT);

    const dim3 gemm_grid(S_LEN / TCH_T, 3);

    // Layer 0 input projection: x is [B, S, D] -> strideB = S*D, strideT = D
    gemm_mma_kernel<<<gemm_grid, 256, SM_TOT>>>(x, W_ih0, b_ih0, xp,
                                                (long)S_LEN * H_SZ, (long)H_SZ);
    // Layer 0 recurrence (writes y0)
    recur_kernel<<<B_SZ, 384>>>(xp, W_hh0, b_hh0, 1, nullptr, nullptr, nullptr);

    // Layer 1 input projection: y0 is [(t*B + b)*H] -> strideB = H, strideT = B*H
    gemm_mma_kernel<<<gemm_grid, 256, SM_TOT>>>(y0, W_ih1, b_ih1, xp,
                                                (long)H_SZ, (long)B_SZ * H_SZ);
    // Layer 1 recurrence + fused output linear
    recur_kernel<<<B_SZ, 384>>>(xp, W_hh1, b_hh1, 0, W_out, b_out, out);
}

// round 15
// speedup vs baseline: 1.0828x; 1.0828x over previous
#include <cuda_runtime.h>
#include <cuda_bf16.h>
#include <cstdint>

// Problem constants
#define S_LEN 2048
#define B_SZ  128
#define H_SZ  128
#define G_SZ  384   // 3*H
#define C_SZ  10
#define NSM   148   // GB300 SM count (persistent GEMM grid)
#define NUNIT (3 * S_LEN)   // gemm work units: (gate-block, timestep)

// Scratch: xp (input projections, reused by both layers) and y0 (layer-0 output seq)
__device__ float g_xp[(size_t)S_LEN * B_SZ * G_SZ];   // [(t*B + b)*3H + g]
__device__ float g_y0[(size_t)S_LEN * B_SZ * H_SZ];   // [(t*B + b)*H + j]

// ---- packed dual-fp32 helpers -------------------------------------------
__device__ __forceinline__ unsigned long long fma2(unsigned long long a,
                                                   unsigned long long b,
                                                   unsigned long long c) {
    unsigned long long d;
    asm("fma.rn.f32x2 %0, %1, %2, %3;" : "=l"(d) : "l"(a), "l"(b), "l"(c));
    return d;
}
__device__ __forceinline__ float lo32(unsigned long long v) {
    return __uint_as_float((unsigned)(v & 0xffffffffull));
}
__device__ __forceinline__ float hi32(unsigned long long v) {
    return __uint_as_float((unsigned)(v >> 32));
}

// ---- mma.sync / ldmatrix helpers (plain sm_80+ features, no 'a'-gating) ---
__device__ __forceinline__ uint32_t smem_u32(const void* p) {
    uint32_t a;
    asm("{ .reg .u64 t; cvta.to.shared.u64 t, %1; cvt.u32.u64 %0, t; }"
        : "=r"(a) : "l"(p));
    return a;
}
__device__ __forceinline__ void ldmx4(uint32_t* r, uint32_t addr) {
    asm volatile("ldmatrix.sync.aligned.m8n8.x4.shared.b16 {%0,%1,%2,%3}, [%4];"
                 : "=r"(r[0]), "=r"(r[1]), "=r"(r[2]), "=r"(r[3]) : "r"(addr));
}
__device__ __forceinline__ void mma_bf16(float* c, const uint32_t* a,
                                         uint32_t b0, uint32_t b1) {
    asm volatile(
        "mma.sync.aligned.m16n8k16.row.col.f32.bf16.bf16.f32 "
        "{%0,%1,%2,%3}, {%4,%5,%6,%7}, {%8,%9}, {%0,%1,%2,%3};"
        : "+f"(c[0]), "+f"(c[1]), "+f"(c[2]), "+f"(c[3])
        : "r"(a[0]), "r"(a[1]), "r"(a[2]), "r"(a[3]), "r"(b0), "r"(b1));
}

// Split one float4 into bf16 hi + lo pairs (packed as uint2 = 4 bf16)
__device__ __forceinline__ void split4(float4 v, uint2& hi, uint2& lo) {
    __nv_bfloat162 h01 = __floats2bfloat162_rn(v.x, v.y);
    __nv_bfloat162 h23 = __floats2bfloat162_rn(v.z, v.w);
    const float r0 = v.x - __bfloat162float(h01.x);
    const float r1 = v.y - __bfloat162float(h01.y);
    const float r2 = v.z - __bfloat162float(h23.x);
    const float r3 = v.w - __bfloat162float(h23.y);
    __nv_bfloat162 l01 = __floats2bfloat162_rn(r0, r1);
    __nv_bfloat162 l23 = __floats2bfloat162_rn(r2, r3);
    hi = make_uint2(*reinterpret_cast<uint32_t*>(&h01), *reinterpret_cast<uint32_t*>(&h23));
    lo = make_uint2(*reinterpret_cast<uint32_t*>(&l01), *reinterpret_cast<uint32_t*>(&l23));
}

// SMEM layout (bytes): bias + 2x double-buffered X tiles + W tiles, pitch 272 B
#define PITCHB 272
#define TILEB  (128 * PITCHB)          // 34816
#define SM_BIAS 0
#define SM_XHI0 512
#define SM_XLO0 (SM_XHI0 + TILEB)
#define SM_XHI1 (SM_XLO0 + TILEB)
#define SM_XLO1 (SM_XHI1 + TILEB)
#define SM_WHI  (SM_XLO1 + TILEB)
#define SM_WLO  (SM_WHI + TILEB)
#define SM_TOT  (SM_WLO + TILEB)       // 209408

// ---------------------------------------------------------------------------
// Persistent tensor-core input-projection GEMM via mma.sync.
// Grid = 148 CTAs; work = 6144 units, unit u = gb*2048 + t (gate-block gb,
// timestep t). Each CTA owns a contiguous unit range (41-42 units, <=1 W
// restage). Removes the 2.59-wave tail of the old 384-CTA launch.
// X tiles software-pipelined (next unit's LDG under current MMA block);
// ldmatrix fragments double-buffered within each split.
// ---------------------------------------------------------------------------
__global__ __launch_bounds__(256, 1)
void gemm_mma_kernel(const float* __restrict__ in,
                     const float* __restrict__ W,
                     const float* __restrict__ bias,
                     float* __restrict__ out,
                     long strideB, long strideT)
{
    extern __shared__ __align__(16) char smem[];
    const uint32_t sb = smem_u32(smem);
    float* sbias = reinterpret_cast<float*>(smem + SM_BIAS);

    const int tid  = threadIdx.x;
    const int w    = tid >> 5;
    const int lane = tid & 31;
    const int c    = blockIdx.x;

    const int u0 = (c * NUNIT) / NSM;
    const int u1 = ((c + 1) * NUNIT) / NSM;

    // ---- W/bias staging for a gate block (callers handle syncs) ----
    auto stage_w = [&](int gb) {
        const int g0 = gb * 128;
        if (tid < 128) sbias[tid] = bias[g0 + tid];
        for (int i = tid; i < 128 * 32; i += 256) {
            const int row = i >> 5, c4 = i & 31;
            const float4 v = *reinterpret_cast<const float4*>(
                W + (size_t)(g0 + row) * H_SZ + c4 * 4);
            uint2 hi, lo;
            split4(v, hi, lo);
            const int off = row * PITCHB + c4 * 8;
            *reinterpret_cast<uint2*>(smem + SM_WHI + off) = hi;
            *reinterpret_cast<uint2*>(smem + SM_WLO + off) = lo;
        }
    };

    int gb_cur = u0 / S_LEN;
    stage_w(gb_cur);

    // Prologue: stage X tile for first unit into buffer 0
    {
        const int t0 = u0 % S_LEN;
#pragma unroll
        for (int k = 0; k < 16; k++) {
            const int i = tid + k * 256;
            const int row = i >> 5, c4 = i & 31;
            const float4 v = *reinterpret_cast<const float4*>(
                in + (size_t)row * strideB + (size_t)t0 * strideT + c4 * 4);
            uint2 hi, lo;
            split4(v, hi, lo);
            const int off = row * PITCHB + c4 * 8;
            *reinterpret_cast<uint2*>(smem + SM_XHI0 + off) = hi;
            *reinterpret_cast<uint2*>(smem + SM_XLO0 + off) = lo;
        }
    }
    __syncthreads();

    const int mBase = (w & 1) * 64;
    const int nBase = (w >> 1) * 32;

    uint32_t aoff[4];
#pragma unroll
    for (int mt = 0; mt < 4; mt++)
        aoff[mt] = (uint32_t)((mBase + mt * 16 + (lane & 15)) * PITCHB
                              + (lane >> 4) * 16);
    uint32_t boff[2];
#pragma unroll
    for (int nt2 = 0; nt2 < 2; nt2++) {
        const int rt = lane & 7, tl = lane >> 3;
        const int n = nBase + nt2 * 16 + ((tl >> 1) << 3) + rt;
        boff[nt2] = (uint32_t)(n * PITCHB + (tl & 1) * 16);
    }

    for (int u = u0; u < u1; u++) {
        const int t   = u % S_LEN;
        const int cur = (u - u0) & 1;
        const uint32_t xhiC = cur ? SM_XHI1 : SM_XHI0;
        const uint32_t xloC = cur ? SM_XLO1 : SM_XLO0;
        const uint32_t xhiN = cur ? SM_XHI0 : SM_XHI1;
        const uint32_t xloN = cur ? SM_XLO0 : SM_XLO1;
        const int g0 = gb_cur * 128;

        // Issue next unit's X loads NOW (consumed after the MMA block).
        // X staging is gb-independent (t of u+1), so valid across restage.
        float4 v[16];
        const bool more = (u + 1 < u1);
        if (more) {
            const int tn = (u + 1) % S_LEN;
#pragma unroll
            for (int k = 0; k < 16; k++) {
                const int i = tid + k * 256;
                const int row = i >> 5, c4 = i & 31;
                v[k] = *reinterpret_cast<const float4*>(
                    in + (size_t)row * strideB + (size_t)tn * strideT + c4 * 4);
            }
        }

        float acc[4][4][4];
#pragma unroll
        for (int mt = 0; mt < 4; mt++)
#pragma unroll
            for (int nt = 0; nt < 4; nt++)
#pragma unroll
                for (int e = 0; e < 4; e++) acc[mt][nt][e] = 0.0f;

        // 3 splits: Ahi*Whi, Ahi*Wlo, Alo*Whi; frag double-buffered per split
#pragma unroll
        for (int s = 0; s < 3; s++) {
            const uint32_t aS = sb + (s == 2 ? xloC : xhiC);
            const uint32_t bS = sb + (s == 1 ? SM_WLO : SM_WHI);

            uint32_t a[2][4][4], b[2][2][4];
#pragma unroll
            for (int mt = 0; mt < 4; mt++) ldmx4(a[0][mt], aS + aoff[mt]);
#pragma unroll
            for (int nt2 = 0; nt2 < 2; nt2++) ldmx4(b[0][nt2], bS + boff[nt2]);

#pragma unroll
            for (int k16 = 0; k16 < 8; k16++) {
                const int pc = k16 & 1;
                const int pn = pc ^ 1;
                if (k16 < 7) {
                    const uint32_t kb = (uint32_t)((k16 + 1) * 32);
#pragma unroll
                    for (int mt = 0; mt < 4; mt++) ldmx4(a[pn][mt], aS + aoff[mt] + kb);
#pragma unroll
                    for (int nt2 = 0; nt2 < 2; nt2++) ldmx4(b[pn][nt2], bS + boff[nt2] + kb);
                }
#pragma unroll
                for (int mt = 0; mt < 4; mt++)
#pragma unroll
                    for (int nt = 0; nt < 4; nt++)
                        mma_bf16(acc[mt][nt], a[pc][mt],
                                 b[pc][nt >> 1][(nt & 1) * 2],
                                 b[pc][nt >> 1][(nt & 1) * 2 + 1]);
            }
        }

        // Split + store next unit's X tile
        if (more) {
#pragma unroll
            for (int k = 0; k < 16; k++) {
                const int i = tid + k * 256;
                const int row = i >> 5, c4 = i & 31;
                uint2 hi, lo;
                split4(v[k], hi, lo);
                const int off = row * PITCHB + c4 * 8;
                *reinterpret_cast<uint2*>(smem + xhiN + off) = hi;
                *reinterpret_cast<uint2*>(smem + xloN + off) = lo;
            }
        }

        // Write out D + bias
        const int mrow = lane >> 2;
        const int ncol = (lane & 3) * 2;
#pragma unroll
        for (int mt = 0; mt < 4; mt++) {
#pragma unroll
            for (int nt = 0; nt < 4; nt++) {
                const int col = nBase + nt * 8 + ncol;
                const float bv0 = sbias[col], bv1 = sbias[col + 1];
                const int row0 = mBase + mt * 16 + mrow;
                float* p0 = out + ((size_t)t * B_SZ + row0) * G_SZ + g0 + col;
                float* p1 = p0 + (size_t)8 * G_SZ;
                *reinterpret_cast<float2*>(p0) =
                    make_float2(acc[mt][nt][0] + bv0, acc[mt][nt][1] + bv1);
                *reinterpret_cast<float2*>(p1) =
                    make_float2(acc[mt][nt][2] + bv0, acc[mt][nt][3] + bv1);
            }
        }
        __syncthreads();   // MMAs + STS done before buffer/W reuse

        // Gate-block boundary: restage W (all MMAs on old W completed above)
        if (more) {
            const int gb_next = (u + 1) / S_LEN;
            if (gb_next != gb_cur) {
                stage_w(gb_next);
                gb_cur = gb_next;
                __syncthreads();
            }
        }
    }
}

// ---------------------------------------------------------------------------
// Recurrent scan — EXACT Round-1 version (measured best: 1.357 ms/layer;
// four micro-variants all regressed — do not edit).
// One CTA per batch element, 384 threads (one per gate output).
// ---------------------------------------------------------------------------
__global__ __launch_bounds__(384, 1)
void recur_kernel(const float* __restrict__ xp,
                  const float* __restrict__ W_hh,
                  const float* __restrict__ b_hh,
                  int write_y,
                  const float* __restrict__ W_out,
                  const float* __restrict__ b_out,
                  float* __restrict__ out)
{
    __shared__ __align__(16) float h_s[H_SZ];
    __shared__ float hp_s[G_SZ];
    __shared__ float xg_s[G_SZ];

    const int b = blockIdx.x;
    const int g = threadIdx.x;

    unsigned long long w[64];
    const unsigned long long* wrow =
        reinterpret_cast<const unsigned long long*>(W_hh + (size_t)g * H_SZ);
#pragma unroll
    for (int i = 0; i < 64; i++) w[i] = wrow[i];
    const float bh = b_hh[g];

    if (g < H_SZ) h_s[g] = 0.0f;

    const float* xptr = xp + (size_t)b * G_SZ + g;
    float xnext = __ldg(xptr);        // prefetch t=0
    __syncthreads();

    for (int t = 0; t < S_LEN; t++) {
        const float xcur = xnext;
        if (t + 1 < S_LEN)
            xnext = __ldg(xptr + (size_t)(t + 1) * B_SZ * G_SZ);  // prefetch next step

        // hp[g] = h . W_hh[g]
        unsigned long long a0 = 0ull, a1 = 0ull;
        const ulonglong2* hq = reinterpret_cast<const ulonglong2*>(h_s);
#pragma unroll
        for (int i = 0; i < 32; i++) {
            const ulonglong2 q = hq[i];   // broadcast LDS.128
            a0 = fma2(q.x, w[2 * i + 0], a0);
            a1 = fma2(q.y, w[2 * i + 1], a1);
        }
        hp_s[g] = lo32(a0) + hi32(a0) + lo32(a1) + hi32(a1) + bh;
        xg_s[g] = xcur;
        __syncthreads();

        if (g < H_SZ) {
            const float pr = xg_s[g]            + hp_s[g];
            const float pz = xg_s[H_SZ + g]     + hp_s[H_SZ + g];
            const float xn = xg_s[2 * H_SZ + g];
            const float hn = hp_s[2 * H_SZ + g];
            const float r = 1.0f / (1.0f + __expf(-pr));
            const float z = 1.0f / (1.0f + __expf(-pz));
            const float n = tanhf(fmaf(r, hn, xn));
            const float hold = h_s[g];
            const float hnew = (1.0f - z) * n + z * hold;
            h_s[g] = hnew;
            if (write_y)
                g_y0[((size_t)t * B_SZ + b) * H_SZ + g] = hnew;
        }
        __syncthreads();
    }

    // Fused final linear layer (layer 1 only)
    if (!write_y && g < C_SZ) {
        float acc = b_out[g];
#pragma unroll 8
        for (int j = 0; j < H_SZ; j++)
            acc = fmaf(h_s[j], W_out[g * H_SZ + j], acc);
        out[b * C_SZ + g] = acc;
    }
}

// ---------------------------------------------------------------------------
extern "C" void kernel_launch(void* const* d_in, const int* in_sizes, int n_in,
                              void* d_out, int out_size)
{
    const float* x     = (const float*)d_in[0];
    const float* W_ih0 = (const float*)d_in[1];
    const float* W_hh0 = (const float*)d_in[2];
    const float* b_ih0 = (const float*)d_in[3];
    const float* b_hh0 = (const float*)d_in[4];
    const float* W_ih1 = (const float*)d_in[5];
    const float* W_hh1 = (const float*)d_in[6];
    const float* b_ih1 = (const float*)d_in[7];
    const float* b_hh1 = (const float*)d_in[8];
    const float* W_out = (const float*)d_in[9];
    const float* b_out = (const float*)d_in[10];
    float* out = (float*)d_out;

    void* xp_ptr = nullptr;
    void* y0_ptr = nullptr;
    cudaGetSymbolAddress(&xp_ptr, g_xp);
    cudaGetSymbolAddress(&y0_ptr, g_y0);
    float* xp = (float*)xp_ptr;
    float* y0 = (float*)y0_ptr;

    cudaFuncSetAttribute(gemm_mma_kernel,
                         cudaFuncAttributeMaxDynamicSharedMemorySize, SM_TOT);

    // Layer 0 input projection: x is [B, S, D] -> strideB = S*D, strideT = D
    gemm_mma_kernel<<<NSM, 256, SM_TOT>>>(x, W_ih0, b_ih0, xp,
                                          (long)S_LEN * H_SZ, (long)H_SZ);
    // Layer 0 recurrence (writes y0)
    recur_kernel<<<B_SZ, 384>>>(xp, W_hh0, b_hh0, 1, nullptr, nullptr, nullptr);

    // Layer 1 input projection: y0 is [(t*B + b)*H] -> strideB = H, strideT = B*H
    gemm_mma_kernel<<<NSM, 256, SM_TOT>>>(y0, W_ih1, b_ih1, xp,
                                          (long)H_SZ, (long)B_SZ * H_SZ);
    // Layer 1 recurrence + fused output linear
    recur_kernel<<<B_SZ, 384>>>(xp, W_hh1, b_hh1, 0, W_out, b_out, out);
}